// round 15
// baseline (speedup 1.0000x reference)
#include <cuda_runtime.h>
#include <cstdint>

// Problem constants: input (64, 65536, 6) f32, output (64, 640) f32.
#define BATCHES     64
#define POINTS      65536
#define PAIRS       (POINTS / 2)            // 32768 pairs per batch
#define F4_PER_B    (POINTS * 6 / 4)        // 98304 float4 per batch
#define NUM_BINS    4
#define NUM_CELLS   64
#define STATS       10
#define FEAT        (NUM_CELLS * STATS)     // 640

// Kernel 1 (bbox) config — R3 strided config (best measured: ~18.6us).
#define BPB1        32
#define T1          256
#define PAIRS_PER_BLK1 (PAIRS / BPB1)       // 1024
#define ITER1       (PAIRS_PER_BLK1 / T1)   // 4

// Kernel 2 (accumulate) config — R11 per-batch grid, guard-free.
#define BPB2        4                       // 4 x 64 = 256 blocks
#define T2          512
#define PAIRS_PER_BLK2 (PAIRS / BPB2)       // 8192
#define ITER2       (PAIRS_PER_BLK2 / T2)   // 16 pairs/thread -> 8 double-iters
#define REPL        32                      // one replica per lane — required
#define HIST_WORDS  (FEAT * REPL)           // 20480 floats = 80 KB
#define HIST_BYTES  (HIST_WORDS * 4)

// Device scratch (zero at module load; k_final restores zeros after each use
// so every graph replay sees identical initial state).
__device__ unsigned int g_bbox[BATCHES];
__device__ float        g_sums[BATCHES * FEAT];

// ---------------------------------------------------------------------------
// Kernel 1: per-batch bbox_max = max(|pos|), strided pair loads (R3-exact).
// Layout per point pair (12 floats = 3 float4):
//   a = [p0x p0y p0z o0x]  b = [o0y o0z p1x p1y]  c = [p1z o1x o1y o1z]
// ---------------------------------------------------------------------------
__global__ __launch_bounds__(T1) void k_bbox(const float4* __restrict__ in4) {
    const int batch = blockIdx.y;
    const int tid = threadIdx.x;
    const float4* p = in4 + (size_t)batch * F4_PER_B;
    const int base = blockIdx.x * PAIRS_PER_BLK1;

    float m = 0.0f;
#pragma unroll
    for (int k = 0; k < ITER1; k++) {
        int j = base + tid + k * T1;
        float4 a = p[3 * j + 0];
        float4 b = p[3 * j + 1];
        float4 c = p[3 * j + 2];
        m = fmaxf(m, fmaxf(fmaxf(fabsf(a.x), fabsf(a.y)), fabsf(a.z)));
        m = fmaxf(m, fmaxf(fmaxf(fabsf(b.z), fabsf(b.w)), fabsf(c.x)));
    }
    // positive floats: uint order == float order
    unsigned int mu = __reduce_max_sync(0xFFFFFFFFu, __float_as_uint(m));

    __shared__ unsigned int sm[T1 / 32];
    if ((tid & 31) == 0) sm[tid >> 5] = mu;
    __syncthreads();
    if (tid == 0) {
        unsigned int mm = sm[0];
#pragma unroll
        for (int i = 1; i < T1 / 32; i++) mm = max(mm, sm[i]);
        atomicMax(&g_bbox[batch], mm);
        cudaTriggerProgrammaticLaunchCompletion();
    }
}

// ---------------------------------------------------------------------------
// Kernel 2: bin points, accumulate (count, sum_pic, sum_cov) per cell.
// Per-lane replica, bank-exact layout: word = (cell*10+s)*32 + lane.
// ---------------------------------------------------------------------------
extern __shared__ float hist[];   // HIST_WORDS floats (80 KB dynamic)

__device__ __forceinline__ void accum_point(
    float* __restrict__ h,   // hist + lane
    float px, float py, float pz,
    float ox, float oy, float oz,
    float half_c, float inv)
{
    // pic = (p + bbox) * inv = fma(p, inv, half_c) with half_c = bbox*inv
    float picx = fmaf(px, inv, half_c);
    float picy = fmaf(py, inv, half_c);
    float picz = fmaf(pz, inv, half_c);
    int ix = (int)(picx * 4.0f); ix = min(max(ix, 0), 3);
    int iy = (int)(picy * 4.0f); iy = min(max(iy, 0), 3);
    int iz = (int)(picz * 4.0f); iz = min(max(iz, 0), 3);
    int cell = (ix * NUM_BINS + iy) * NUM_BINS + iz;
    float* d = h + cell * (STATS * REPL);
    atomicAdd(d + 0 * REPL, 1.0f);
    atomicAdd(d + 1 * REPL, picx);
    atomicAdd(d + 2 * REPL, picy);
    atomicAdd(d + 3 * REPL, picz);
    atomicAdd(d + 4 * REPL, ox * ox);
    atomicAdd(d + 5 * REPL, ox * oy);
    atomicAdd(d + 6 * REPL, ox * oz);
    atomicAdd(d + 7 * REPL, oy * oy);
    atomicAdd(d + 8 * REPL, oy * oz);
    atomicAdd(d + 9 * REPL, oz * oz);
}

__global__ __launch_bounds__(T2) void k_accum(const float4* __restrict__ in4) {
    const int batch = blockIdx.y;
    const int tid = threadIdx.x;
    const int lane = tid & 31;

    // PDL preamble: zero histogram before waiting on k_bbox (overlaps with
    // the bbox kernel's tail).
    float4* h4 = (float4*)hist;
#pragma unroll
    for (int i = tid; i < HIST_WORDS / 4; i += T2)
        h4[i] = make_float4(0.f, 0.f, 0.f, 0.f);

    cudaGridDependencySynchronize();   // wait: k_bbox complete + visible
    __syncthreads();

    const float bbox = __uint_as_float(g_bbox[batch]);
    const float inv = 1.0f / fmaxf(2.0f * bbox, 1e-5f);
    const float half_c = bbox * inv;

    const float4* p = in4 + (size_t)batch * F4_PER_B;
    const int base = blockIdx.x * PAIRS_PER_BLK2;
    float* hrep = hist + lane;

    // 2 pairs per iteration: all 6 LDG.128 issue before the 40 atomics, so
    // the LSU always has loads in flight behind the atomic stream.
#pragma unroll
    for (int k = 0; k < ITER2 / 2; k++) {
        int j0 = base + tid + (2 * k) * T2;
        int j1 = j0 + T2;
        float4 a0 = p[3 * j0 + 0];
        float4 b0 = p[3 * j0 + 1];
        float4 c0 = p[3 * j0 + 2];
        float4 a1 = p[3 * j1 + 0];
        float4 b1 = p[3 * j1 + 1];
        float4 c1 = p[3 * j1 + 2];
        accum_point(hrep, a0.x, a0.y, a0.z, a0.w, b0.x, b0.y, half_c, inv);
        accum_point(hrep, b0.z, b0.w, c0.x, c0.y, c0.z, c0.w, half_c, inv);
        accum_point(hrep, a1.x, a1.y, a1.z, a1.w, b1.x, b1.y, half_c, inv);
        accum_point(hrep, b1.z, b1.w, c1.x, c1.y, c1.z, c1.w, half_c, inv);
    }
    __syncthreads();

    // Reduce 32 replicas per feature; rotate replica order by lane so the
    // 32 lanes of a warp hit 32 distinct banks each step.
    for (int w = tid; w < FEAT; w += T2) {
        float s = 0.0f;
#pragma unroll
        for (int r = 0; r < REPL; r++)
            s += hist[w * REPL + ((r + lane) & 31)];
        atomicAdd(&g_sums[batch * FEAT + w], s);
    }
    __syncthreads();
    if (tid == 0) cudaTriggerProgrammaticLaunchCompletion();
}

// ---------------------------------------------------------------------------
// Kernel 3: finalize. One block per batch, 640 threads = one (cell, stat).
// L2-normalize the 640-vector; restore scratch to zero for next replay.
// ---------------------------------------------------------------------------
__global__ __launch_bounds__(FEAT) void k_final(float* __restrict__ out) {
    cudaGridDependencySynchronize();   // wait: k_accum complete + visible

    const int b = blockIdx.x;
    const int t = threadIdx.x;               // 0..639
    const int cell = t / STATS;
    const int s = t - cell * STATS;

    float* sums = g_sums + b * FEAT;
    float cnt = sums[cell * STATS];
    float val = sums[t];
    float fc = fmaxf(cnt, 1.0f);
    float up = rsqrtf(fc);

    float f;
    if (s == 0) {
        f = 0.001f * cnt * up;
    } else if (s < 4) {
        int d = s - 1;
        int ci = (d == 0) ? (cell >> 4) : (d == 1) ? ((cell >> 2) & 3) : (cell & 3);
        float g = ((float)ci + 0.5f) * 0.25f;
        f = (val - cnt * g) * up;
    } else {
        f = val / fc;
    }

    float q = f * f;
#pragma unroll
    for (int o = 16; o > 0; o >>= 1)
        q += __shfl_xor_sync(0xFFFFFFFFu, q, o);

    __shared__ float wsum[FEAT / 32];
    __shared__ float s_inv;
    if ((t & 31) == 0) wsum[t >> 5] = q;
    __syncthreads();

    // all reads of g_sums done -> restore zeros for the next replay
    sums[t] = 0.0f;
    if (t == 0) {
        g_bbox[b] = 0u;
        float ss = 0.0f;
#pragma unroll
        for (int i = 0; i < FEAT / 32; i++) ss += wsum[i];
        s_inv = 1.0f / fmaxf(sqrtf(ss), 1e-12f);
    }
    __syncthreads();

    out[b * FEAT + t] = f * s_inv;
}

// ---------------------------------------------------------------------------
extern "C" void kernel_launch(void* const* d_in, const int* in_sizes, int n_in,
                              void* d_out, int out_size) {
    const float4* in4 = (const float4*)d_in[0];
    float* out = (float*)d_out;
    (void)in_sizes; (void)n_in; (void)out_size;

    cudaFuncSetAttribute(k_accum, cudaFuncAttributeMaxDynamicSharedMemorySize,
                         HIST_BYTES);

    // k_bbox: normal launch (producer).
    k_bbox<<<dim3(BPB1, BATCHES), T1>>>(in4);

    // k_accum: programmatic dependent launch on k_bbox.
    {
        cudaLaunchAttribute a[1];
        a[0].id = cudaLaunchAttributeProgrammaticStreamSerialization;
        a[0].val.programmaticStreamSerializationAllowed = 1;
        cudaLaunchConfig_t cfg{};
        cfg.gridDim = dim3(BPB2, BATCHES);
        cfg.blockDim = dim3(T2);
        cfg.dynamicSmemBytes = HIST_BYTES;
        cfg.stream = 0;
        cfg.attrs = a;
        cfg.numAttrs = 1;
        cudaLaunchKernelEx(&cfg, k_accum, in4);
    }

    // k_final: programmatic dependent launch on k_accum.
    {
        cudaLaunchAttribute a[1];
        a[0].id = cudaLaunchAttributeProgrammaticStreamSerialization;
        a[0].val.programmaticStreamSerializationAllowed = 1;
        cudaLaunchConfig_t cfg{};
        cfg.gridDim = dim3(BATCHES);
        cfg.blockDim = dim3(FEAT);
        cfg.dynamicSmemBytes = 0;
        cfg.stream = 0;
        cfg.attrs = a;
        cfg.numAttrs = 1;
        cudaLaunchKernelEx(&cfg, k_final, out);
    }
}